// round 4
// baseline (speedup 1.0000x reference)
#include <cuda_runtime.h>
#include <math.h>

#define NN    20000
#define KK    32
#define DD    128
#define VOCAB 100000

// ---------------- scratch (static device globals: allocation-free) ----------------
__device__ float g_T[(size_t)VOCAB * DD];   // 51.2 MB: T[v][d] = sum_i u2e[v][i] * W1[d, i]
__device__ float g_C[(size_t)NN * DD];      // 10.2 MB: C[n][d] = b1[d] + sum_i self[i] * W1[d, 128+i]
__device__ float g_W1aT[DD * DD];           // [i][d] = W1[d*256 + i]
__device__ float g_W1bT[DD * DD];           // [i][d] = W1[d*256 + 128 + i]
__device__ float g_W2T[DD * DD];            // [d][e] = W2[e*128 + d]

// ---------------- smem layouts ----------------
struct SG {                 // GEMM kernel (T and C precompute)
    float wt[DD * DD];      // [i][e], reduction-major
    float at[DD * 68];      // [i][r], 64 rows + pad 4
};
struct SK {                 // main per-node kernel (2 nodes / block = 64 edge-rows)
    float w2t[DD * DD];     // [i][e]
    float h1t[DD * 68];     // [i][r]
    float b2s[DD];
    float w3s[DD];
    float logit[64];
    float att[64];
    int   idx[64];
    int   nodeid[2];
    int   len[2];
};

__device__ __forceinline__ float wmaxf(float v) {
    #pragma unroll
    for (int o = 16; o; o >>= 1) v = fmaxf(v, __shfl_xor_sync(0xffffffffu, v, o));
    return v;
}
__device__ __forceinline__ float wsumf(float v) {
    #pragma unroll
    for (int o = 16; o; o >>= 1) v += __shfl_xor_sync(0xffffffffu, v, o);
    return v;
}

// ---------------- K0: transpose weights into reduction-major global copies ----------------
__global__ void prep_kernel(const float* __restrict__ W1, const float* __restrict__ W2) {
    int t = blockIdx.x * blockDim.x + threadIdx.x;
    if (t < DD * DD) {
        int e = t & 127;     // output column
        int i = t >> 7;      // reduction index
        g_W1aT[t] = W1[e * 256 + i];
        g_W1bT[t] = W1[e * 256 + 128 + i];
        g_W2T[t]  = W2[e * 128 + i];
    }
}

// ---------------- K1/K2: out[row][e] = bias[e] + sum_i feats[rowid][i] * WT[i][e] ----------------
// 64 rows x 128 cols per block, 256 threads, per-thread 4x8 tile.
__global__ __launch_bounds__(256, 2)
void mlp_rows_kernel(const float* __restrict__ feats, const int* __restrict__ gather,
                     int nrows, const float* __restrict__ bias, int mode) {
    extern __shared__ unsigned char smem_raw[];
    SG* s = reinterpret_cast<SG*>(smem_raw);
    const float* __restrict__ WT = (mode == 0) ? g_W1aT : g_W1bT;
    float* __restrict__ out      = (mode == 0) ? g_T    : g_C;

    int t = threadIdx.x;
    int r0blk = blockIdx.x * 64;

    // load WT straight (conflict-free float4 copy)
    {
        const float4* src = reinterpret_cast<const float4*>(WT);
        float4* dst = reinterpret_cast<float4*>(s->wt);
        #pragma unroll
        for (int q = t; q < DD * DD / 4; q += 256) dst[q] = src[q];
    }
    // fill at[i][r] transposed: thread r = t%64 loads its row's float4s, scatters scalars
    {
        int r = t & 63, iseg = t >> 6;
        int row = r0blk + r;
        bool ok = row < nrows;
        int rowid = ok ? (gather ? gather[row] : row) : 0;
        const float4* frow = reinterpret_cast<const float4*>(feats + (size_t)rowid * DD);
        #pragma unroll
        for (int j = 0; j < 8; j++) {
            int i4 = iseg * 8 + j;
            float4 v = ok ? frow[i4] : make_float4(0.f, 0.f, 0.f, 0.f);
            int i = i4 * 4;
            s->at[(i + 0) * 68 + r] = v.x;
            s->at[(i + 1) * 68 + r] = v.y;
            s->at[(i + 2) * 68 + r] = v.z;
            s->at[(i + 3) * 68 + r] = v.w;
        }
    }
    __syncthreads();

    int w = t >> 5, lane = t & 31;
    int wr = w & 1,  we = w >> 1;
    int lr = lane & 7, le = lane >> 3;
    int r0 = wr * 32 + lr * 4;
    int e0 = we * 32 + le * 8;

    float acc[4][8];
    #pragma unroll
    for (int a = 0; a < 4; a++)
        #pragma unroll
        for (int b = 0; b < 8; b++) acc[a][b] = 0.f;

    #pragma unroll 4
    for (int i = 0; i < DD; i++) {
        float4 av4 = *reinterpret_cast<const float4*>(&s->at[i * 68 + r0]);
        float4 b0  = *reinterpret_cast<const float4*>(&s->wt[i * DD + e0]);
        float4 b1v = *reinterpret_cast<const float4*>(&s->wt[i * DD + e0 + 4]);
        float av[4] = {av4.x, av4.y, av4.z, av4.w};
        float bv[8] = {b0.x, b0.y, b0.z, b0.w, b1v.x, b1v.y, b1v.z, b1v.w};
        #pragma unroll
        for (int ri = 0; ri < 4; ri++)
            #pragma unroll
            for (int ei = 0; ei < 8; ei++)
                acc[ri][ei] = fmaf(av[ri], bv[ei], acc[ri][ei]);
    }

    #pragma unroll
    for (int ri = 0; ri < 4; ri++) {
        int row = r0blk + r0 + ri;
        if (row >= nrows) continue;
        float* o = out + (size_t)row * DD + e0;
        #pragma unroll
        for (int ei = 0; ei < 8; ei++) {
            float v = acc[ri][ei];
            if (bias) v += bias[e0 + ei];
            o[ei] = v;
        }
    }
}

// ---------------- K3: per 2 nodes (64 edge-rows): h1=relu(T[idx]+C), h2=relu(W2 h1+b2),
//                     logits=W3.h2+b3, masked softmax, attention-weighted aggregation ----------------
__global__ __launch_bounds__(256, 2)
void graphrec_kernel(const float* __restrict__ u2e, const int* __restrict__ nodes,
                     const int* __restrict__ nidx, const int* __restrict__ nlen,
                     const float* __restrict__ b2, const float* __restrict__ W3,
                     const float* __restrict__ b3, float* __restrict__ out) {
    extern __shared__ unsigned char smem_raw[];
    SK* s = reinterpret_cast<SK*>(smem_raw);
    int t = threadIdx.x;
    int nb = blockIdx.x * 2;

    if (t < 64) { s->idx[t] = nidx[nb * KK + t]; s->logit[t] = 0.f; }
    if (t < 2)  { s->nodeid[t] = nodes[nb + t]; s->len[t] = nlen[nb + t]; }
    if (t >= 64 && t < 192) { int e = t - 64; s->b2s[e] = b2[e]; s->w3s[e] = W3[e]; }
    __syncthreads();   // idx needed for h1 fill

    // W2T straight copy
    {
        const float4* src = reinterpret_cast<const float4*>(g_W2T);
        float4* dst = reinterpret_cast<float4*>(s->w2t);
        #pragma unroll
        for (int q = t; q < DD * DD / 4; q += 256) dst[q] = src[q];
    }
    // h1t[i][r] = relu(T[idx[r]][i] + C[node(r)][i])
    {
        int r = t & 63, iseg = t >> 6;
        int vrow = s->idx[r];
        int n = nb + (r >> 5);
        const float4* trow = reinterpret_cast<const float4*>(g_T + (size_t)vrow * DD);
        const float4* crow = reinterpret_cast<const float4*>(g_C + (size_t)n * DD);
        #pragma unroll
        for (int j = 0; j < 8; j++) {
            int i4 = iseg * 8 + j;
            float4 tv = trow[i4];
            float4 cv = crow[i4];
            int i = i4 * 4;
            s->h1t[(i + 0) * 68 + r] = fmaxf(tv.x + cv.x, 0.f);
            s->h1t[(i + 1) * 68 + r] = fmaxf(tv.y + cv.y, 0.f);
            s->h1t[(i + 2) * 68 + r] = fmaxf(tv.z + cv.z, 0.f);
            s->h1t[(i + 3) * 68 + r] = fmaxf(tv.w + cv.w, 0.f);
        }
    }
    __syncthreads();

    int w = t >> 5, lane = t & 31;
    int wr = w & 1,  we = w >> 1;
    int lr = lane & 7, le = lane >> 3;
    int r0 = wr * 32 + lr * 4;
    int e0 = we * 32 + le * 8;

    float acc[4][8];
    #pragma unroll
    for (int a = 0; a < 4; a++)
        #pragma unroll
        for (int b = 0; b < 8; b++) acc[a][b] = 0.f;

    #pragma unroll 4
    for (int i = 0; i < DD; i++) {
        float4 av4 = *reinterpret_cast<const float4*>(&s->h1t[i * 68 + r0]);
        float4 b0  = *reinterpret_cast<const float4*>(&s->w2t[i * DD + e0]);
        float4 b1v = *reinterpret_cast<const float4*>(&s->w2t[i * DD + e0 + 4]);
        float av[4] = {av4.x, av4.y, av4.z, av4.w};
        float bv[8] = {b0.x, b0.y, b0.z, b0.w, b1v.x, b1v.y, b1v.z, b1v.w};
        #pragma unroll
        for (int ri = 0; ri < 4; ri++)
            #pragma unroll
            for (int ei = 0; ei < 8; ei++)
                acc[ri][ei] = fmaf(av[ri], bv[ei], acc[ri][ei]);
    }

    // epilogue: h2 = relu(acc + b2); partial logit = sum_e W3[e]*h2
    float pl[4] = {0.f, 0.f, 0.f, 0.f};
    #pragma unroll
    for (int ri = 0; ri < 4; ri++)
        #pragma unroll
        for (int ei = 0; ei < 8; ei++) {
            float h2 = fmaxf(acc[ri][ei] + s->b2s[e0 + ei], 0.f);
            pl[ri] = fmaf(s->w3s[e0 + ei], h2, pl[ri]);
        }
    #pragma unroll
    for (int ri = 0; ri < 4; ri++) atomicAdd(&s->logit[r0 + ri], pl[ri]);
    __syncthreads();

    // masked softmax over K, one warp per node
    if (w < 2) {
        int nn = w;
        int len = s->len[nn];
        float lg = s->logit[nn * KK + lane] + b3[0];
        bool valid = lane < len;
        float v = valid ? lg : -3.0e38f;
        float m = wmaxf(v);
        float ex = valid ? expf(lg - m) : 0.f;
        float sm = wsumf(ex);
        s->att[nn * KK + lane] = (len > 0) ? (ex / sm) : 0.f;
    }
    __syncthreads();

    // aggregation + output: thread -> (node nn, dim d)
    {
        int nn = t >> 7;
        int d  = t & 127;
        int n = nb + nn;
        float self = u2e[(size_t)s->nodeid[nn] * DD + d];
        float o;
        if (s->len[nn] > 0) {
            float agg = 0.f;
            #pragma unroll
            for (int k = 0; k < KK; k++)
                agg = fmaf(s->att[nn * KK + k], u2e[(size_t)s->idx[nn * KK + k] * DD + d], agg);
            o = 0.5f * (agg + self);
        } else {
            o = self;
        }
        out[(size_t)n * DD + d] = o;
    }
}

// ---------------- launcher ----------------
extern "C" void kernel_launch(void* const* d_in, const int* in_sizes, int n_in,
                              void* d_out, int out_size) {
    const int*   nodes = (const int*)d_in[0];
    const int*   nidx  = (const int*)d_in[1];
    const int*   nlen  = (const int*)d_in[2];
    const float* u2e   = (const float*)d_in[3];
    const float* W1    = (const float*)d_in[4];
    const float* b1    = (const float*)d_in[5];
    const float* W2    = (const float*)d_in[6];
    const float* b2    = (const float*)d_in[7];
    const float* W3    = (const float*)d_in[8];
    const float* b3    = (const float*)d_in[9];
    float* out = (float*)d_out;

    cudaFuncSetAttribute(mlp_rows_kernel, cudaFuncAttributeMaxDynamicSharedMemorySize, (int)sizeof(SG));
    cudaFuncSetAttribute(graphrec_kernel, cudaFuncAttributeMaxDynamicSharedMemorySize, (int)sizeof(SK));

    prep_kernel<<<(DD * DD + 255) / 256, 256>>>(W1, W2);
    mlp_rows_kernel<<<(VOCAB + 63) / 64, 256, sizeof(SG)>>>(u2e, nullptr, VOCAB, nullptr, 0);
    mlp_rows_kernel<<<(NN + 63) / 64, 256, sizeof(SG)>>>(u2e, nodes, NN, b1, 1);
    graphrec_kernel<<<NN / 2, 256, sizeof(SK)>>>(u2e, nodes, nidx, nlen, b2, W3, b3, out);
}

// round 7
// speedup vs baseline: 1.5465x; 1.5465x over previous
#include <cuda_runtime.h>
#include <math.h>
#include <stdint.h>

#define NN    20000
#define KK    32
#define DD    128
#define VOCAB 100000

// ---------------- scratch (static device globals: allocation-free) ----------------
__device__ float g_T[(size_t)VOCAB * DD];   // 51.2 MB: T[v][d] = sum_i u2e[v][i] * W1[d, i]
__device__ float g_C[(size_t)NN * DD];      // 10.2 MB: C[n][d] = b1[d] + sum_i self[i] * W1[d, 128+i]
__device__ float g_W1aT[DD * DD];           // [i][d] = W1[d*256 + i]
__device__ float g_W1bT[DD * DD];           // [i][d] = W1[d*256 + 128 + i]
__device__ float g_W2T[DD * DD];            // [k][e] = W2[e*128 + k]  (reduction-major)

// ---------------- smem layouts ----------------
struct SG {                 // GEMM kernel (T and C precompute), unchanged from R3 (passing)
    float wt[DD * DD];      // [i][e], reduction-major
    float at[DD * 68];      // [i][r], 64 rows + pad 4
};

#define ASTRIDE 132         // 132 mod 32 == 4  -> A-fragment LDS conflict-free
#define BSTRIDE 136         // 136 mod 32 == 8  -> B-fragment LDS conflict-free
struct SK {                 // main kernel: task-looped, W2T staged once per block
    uint32_t b[DD * BSTRIDE];   // tf32 W2T [k][n]           (69632 B)
    uint32_t a[64 * ASTRIDE];   // tf32 h1  [r][k]           (33792 B)
    float b2s[DD];
    float w3s[DD];
    float logit[64];
    float att[64];
    int   idx[64];
    int   nodeid[2];
    int   len[2];
};

__device__ __forceinline__ float wmaxf(float v) {
    #pragma unroll
    for (int o = 16; o; o >>= 1) v = fmaxf(v, __shfl_xor_sync(0xffffffffu, v, o));
    return v;
}
__device__ __forceinline__ float wsumf(float v) {
    #pragma unroll
    for (int o = 16; o; o >>= 1) v += __shfl_xor_sync(0xffffffffu, v, o);
    return v;
}
__device__ __forceinline__ uint32_t f2tf32(float f) {
    uint32_t r;
    asm("cvt.rna.tf32.f32 %0, %1;" : "=r"(r) : "f"(f));
    return r;
}
__device__ __forceinline__ void mma_tf32(float c[4],
                                         uint32_t a0, uint32_t a1, uint32_t a2, uint32_t a3,
                                         uint32_t b0, uint32_t b1) {
    asm volatile(
        "mma.sync.aligned.m16n8k8.row.col.f32.tf32.tf32.f32 "
        "{%0,%1,%2,%3}, {%4,%5,%6,%7}, {%8,%9}, {%0,%1,%2,%3};"
        : "+f"(c[0]), "+f"(c[1]), "+f"(c[2]), "+f"(c[3])
        : "r"(a0), "r"(a1), "r"(a2), "r"(a3), "r"(b0), "r"(b1));
}

// ---------------- K0: transpose weights into reduction-major global copies ----------------
__global__ void prep_kernel(const float* __restrict__ W1, const float* __restrict__ W2) {
    int t = blockIdx.x * blockDim.x + threadIdx.x;
    if (t < DD * DD) {
        int e = t & 127;     // output column
        int i = t >> 7;      // reduction index
        g_W1aT[t] = W1[e * 256 + i];
        g_W1bT[t] = W1[e * 256 + 128 + i];
        g_W2T[t]  = W2[e * 128 + i];
    }
}

// ---------------- K1/K2: out[row][e] = bias[e] + sum_i feats[rowid][i] * WT[i][e] ----------------
__global__ __launch_bounds__(256, 2)
void mlp_rows_kernel(const float* __restrict__ feats, const int* __restrict__ gather,
                     int nrows, const float* __restrict__ bias, int mode) {
    extern __shared__ unsigned char smem_raw[];
    SG* s = reinterpret_cast<SG*>(smem_raw);
    const float* __restrict__ WT = (mode == 0) ? g_W1aT : g_W1bT;
    float* __restrict__ out      = (mode == 0) ? g_T    : g_C;

    int t = threadIdx.x;
    int r0blk = blockIdx.x * 64;

    {
        const float4* src = reinterpret_cast<const float4*>(WT);
        float4* dst = reinterpret_cast<float4*>(s->wt);
        #pragma unroll
        for (int q = t; q < DD * DD / 4; q += 256) dst[q] = src[q];
    }
    {
        int r = t & 63, iseg = t >> 6;
        int row = r0blk + r;
        bool ok = row < nrows;
        int rowid = ok ? (gather ? gather[row] : row) : 0;
        const float4* frow = reinterpret_cast<const float4*>(feats + (size_t)rowid * DD);
        #pragma unroll
        for (int j = 0; j < 8; j++) {
            int i4 = iseg * 8 + j;
            float4 v = ok ? frow[i4] : make_float4(0.f, 0.f, 0.f, 0.f);
            int i = i4 * 4;
            s->at[(i + 0) * 68 + r] = v.x;
            s->at[(i + 1) * 68 + r] = v.y;
            s->at[(i + 2) * 68 + r] = v.z;
            s->at[(i + 3) * 68 + r] = v.w;
        }
    }
    __syncthreads();

    int w = t >> 5, lane = t & 31;
    int wr = w & 1,  we = w >> 1;
    int lr = lane & 7, le = lane >> 3;
    int r0 = wr * 32 + lr * 4;
    int e0 = we * 32 + le * 8;

    float acc[4][8];
    #pragma unroll
    for (int a = 0; a < 4; a++)
        #pragma unroll
        for (int b = 0; b < 8; b++) acc[a][b] = 0.f;

    #pragma unroll 4
    for (int i = 0; i < DD; i++) {
        float4 av4 = *reinterpret_cast<const float4*>(&s->at[i * 68 + r0]);
        float4 b0  = *reinterpret_cast<const float4*>(&s->wt[i * DD + e0]);
        float4 b1v = *reinterpret_cast<const float4*>(&s->wt[i * DD + e0 + 4]);
        float av[4] = {av4.x, av4.y, av4.z, av4.w};
        float bv[8] = {b0.x, b0.y, b0.z, b0.w, b1v.x, b1v.y, b1v.z, b1v.w};
        #pragma unroll
        for (int ri = 0; ri < 4; ri++)
            #pragma unroll
            for (int ei = 0; ei < 8; ei++)
                acc[ri][ei] = fmaf(av[ri], bv[ei], acc[ri][ei]);
    }

    #pragma unroll
    for (int ri = 0; ri < 4; ri++) {
        int row = r0blk + r0 + ri;
        if (row >= nrows) continue;
        float* o = out + (size_t)row * DD + e0;
        #pragma unroll
        for (int ei = 0; ei < 8; ei++) {
            float v = acc[ri][ei];
            if (bias) v += bias[e0 + ei];
            o[ei] = v;
        }
    }
}

// ---------------- K3: task-looped; layer-2 on tensor cores (tf32 mma.sync) ----------------
// Per task (2 nodes = 64 edge rows):
//   h1 = relu(T[idx] + C[node])  -> tf32 smem [64][ASTRIDE]
//   C64x128 = h1 @ W2T           -> mma.sync m16n8k8 tf32, 8 warps of 16x64 tiles
//   logits -> masked softmax -> attention-weighted aggregation (exact fp32)
__global__ __launch_bounds__(256, 2)
void graphrec_kernel(const float* __restrict__ u2e, const int* __restrict__ nodes,
                     const int* __restrict__ nidx, const int* __restrict__ nlen,
                     const float* __restrict__ b2, const float* __restrict__ W3,
                     const float* __restrict__ b3, float* __restrict__ out,
                     int ntasks) {
    extern __shared__ unsigned char smem_raw[];
    SK* s = reinterpret_cast<SK*>(smem_raw);
    int t = threadIdx.x;
    int w = t >> 5, lane = t & 31;
    int grp = lane >> 2, tig = lane & 3;
    int rw = (w & 3) * 16;       // warp row block within 64
    int cw = (w >> 2) * 64;      // warp col block within 128

    // ---- one-time per block: stage W2T (tf32), b2, W3 ----
    for (int q = t; q < DD * DD; q += 256) {
        int k = q >> 7, n = q & 127;
        s->b[k * BSTRIDE + n] = f2tf32(g_W2T[q]);
    }
    if (t < DD) { s->b2s[t] = b2[t]; s->w3s[t] = W3[t]; }
    float b3v = b3[0];

    for (int task = blockIdx.x; task < ntasks; task += gridDim.x) {
        __syncthreads();   // protects prev iteration's smem reads before overwrite

        if (t < 64) { s->idx[t] = nidx[task * 64 + t]; s->logit[t] = 0.f; }
        if (t < 2)  { s->nodeid[t] = nodes[task * 2 + t]; s->len[t] = nlen[task * 2 + t]; }
        __syncthreads();

        // ---- fill h1 (tf32): 4 threads per row, each 32 contiguous floats ----
        {
            int r = t >> 2, q = t & 3;
            int vrow = s->idx[r];
            int n = task * 2 + (r >> 5);
            const float4* trow = reinterpret_cast<const float4*>(g_T + (size_t)vrow * DD) + q * 8;
            const float4* crow = reinterpret_cast<const float4*>(g_C + (size_t)n * DD) + q * 8;
            uint4* dst = reinterpret_cast<uint4*>(s->a + r * ASTRIDE + q * 32);
            #pragma unroll
            for (int j = 0; j < 8; j++) {
                float4 tv = trow[j];
                float4 cv = crow[j];
                uint4 o;
                o.x = f2tf32(fmaxf(tv.x + cv.x, 0.f));
                o.y = f2tf32(fmaxf(tv.y + cv.y, 0.f));
                o.z = f2tf32(fmaxf(tv.z + cv.z, 0.f));
                o.w = f2tf32(fmaxf(tv.w + cv.w, 0.f));
                dst[j] = o;
            }
        }
        __syncthreads();

        // ---- tensor-core mainloop: 16 k-steps x 8 n-tiles of m16n8k8 ----
        float acc[8][4];
        #pragma unroll
        for (int nt = 0; nt < 8; nt++)
            #pragma unroll
            for (int c = 0; c < 4; c++) acc[nt][c] = 0.f;

        #pragma unroll
        for (int k0 = 0; k0 < DD; k0 += 8) {
            const uint32_t* ar0 = s->a + (rw + grp) * ASTRIDE + k0 + tig;
            const uint32_t* ar1 = ar0 + 8 * ASTRIDE;
            uint32_t a0 = ar0[0];
            uint32_t a2 = ar0[4];
            uint32_t a1 = ar1[0];
            uint32_t a3 = ar1[4];
            const uint32_t* br0 = s->b + (k0 + tig) * BSTRIDE + cw + grp;
            const uint32_t* br1 = br0 + 4 * BSTRIDE;
            #pragma unroll
            for (int nt = 0; nt < 8; nt++) {
                uint32_t b0 = br0[nt * 8];
                uint32_t b1 = br1[nt * 8];
                mma_tf32(acc[nt], a0, a1, a2, a3, b0, b1);
            }
        }

        // ---- epilogue: h2 = relu(c + b2), partial logit = sum W3*h2 ----
        float pl0 = 0.f, pl1 = 0.f;
        #pragma unroll
        for (int nt = 0; nt < 8; nt++) {
            int c0 = cw + nt * 8 + tig * 2;
            float b2a = s->b2s[c0],     b2b = s->b2s[c0 + 1];
            float w3a = s->w3s[c0],     w3b = s->w3s[c0 + 1];
            pl0 = fmaf(w3a, fmaxf(acc[nt][0] + b2a, 0.f), pl0);
            pl0 = fmaf(w3b, fmaxf(acc[nt][1] + b2b, 0.f), pl0);
            pl1 = fmaf(w3a, fmaxf(acc[nt][2] + b2a, 0.f), pl1);
            pl1 = fmaf(w3b, fmaxf(acc[nt][3] + b2b, 0.f), pl1);
        }
        // reduce over tig (lane bits 0-1)
        pl0 += __shfl_xor_sync(0xffffffffu, pl0, 1);
        pl0 += __shfl_xor_sync(0xffffffffu, pl0, 2);
        pl1 += __shfl_xor_sync(0xffffffffu, pl1, 1);
        pl1 += __shfl_xor_sync(0xffffffffu, pl1, 2);
        if (tig == 0) {
            atomicAdd(&s->logit[rw + grp],     pl0);
            atomicAdd(&s->logit[rw + grp + 8], pl1);
        }
        __syncthreads();

        // ---- masked softmax over K, one warp per node ----
        if (w < 2) {
            int nn = w;
            int len = s->len[nn];
            float lg = s->logit[nn * KK + lane] + b3v;
            bool valid = lane < len;
            float v = valid ? lg : -3.0e38f;
            float m = wmaxf(v);
            float ex = valid ? expf(lg - m) : 0.f;
            float sm = wsumf(ex);
            s->att[nn * KK + lane] = (len > 0) ? (ex / sm) : 0.f;
        }
        __syncthreads();

        // ---- aggregation + output (exact fp32): thread -> (node nn, dim d) ----
        {
            int nn = t >> 7;
            int d  = t & 127;
            int n = task * 2 + nn;
            float self = u2e[(size_t)s->nodeid[nn] * DD + d];
            float o;
            if (s->len[nn] > 0) {
                float agg = 0.f;
                #pragma unroll
                for (int k = 0; k < KK; k++)
                    agg = fmaf(s->att[nn * KK + k], u2e[(size_t)s->idx[nn * KK + k] * DD + d], agg);
                o = 0.5f * (agg + self);
            } else {
                o = self;
            }
            out[(size_t)n * DD + d] = o;
        }
    }
}

// ---------------- launcher ----------------
extern "C" void kernel_launch(void* const* d_in, const int* in_sizes, int n_in,
                              void* d_out, int out_size) {
    const int*   nodes = (const int*)d_in[0];
    const int*   nidx  = (const int*)d_in[1];
    const int*   nlen  = (const int*)d_in[2];
    const float* u2e   = (const float*)d_in[3];
    const float* W1    = (const float*)d_in[4];
    const float* b1    = (const float*)d_in[5];
    const float* W2    = (const float*)d_in[6];
    const float* b2    = (const float*)d_in[7];
    const float* W3    = (const float*)d_in[8];
    const float* b3    = (const float*)d_in[9];
    float* out = (float*)d_out;

    cudaFuncSetAttribute(mlp_rows_kernel, cudaFuncAttributeMaxDynamicSharedMemorySize, (int)sizeof(SG));
    cudaFuncSetAttribute(graphrec_kernel, cudaFuncAttributeMaxDynamicSharedMemorySize, (int)sizeof(SK));

    prep_kernel<<<(DD * DD + 255) / 256, 256>>>(W1, W2);
    mlp_rows_kernel<<<(VOCAB + 63) / 64, 256, sizeof(SG)>>>(u2e, nullptr, VOCAB, nullptr, 0);
    mlp_rows_kernel<<<(NN + 63) / 64, 256, sizeof(SG)>>>(u2e, nodes, NN, b1, 1);
    graphrec_kernel<<<296, 256, sizeof(SK)>>>(u2e, nodes, nidx, nlen, b2, W3, b3, out, NN / 2);
}

// round 9
// speedup vs baseline: 1.8124x; 1.1719x over previous
#include <cuda_runtime.h>
#include <math.h>
#include <stdint.h>

#define NN    20000
#define KK    32
#define DD    128
#define VOCAB 100000

// ---------------- scratch (static device globals: allocation-free) ----------------
__device__ float g_T[(size_t)VOCAB * DD];   // T[v][d] = sum_i u2e[v][i] * W1[d, i]
__device__ float g_C[(size_t)NN * DD];      // C[n][d] = b1[d] + sum_i self[i] * W1[d, 128+i]
__device__ float g_W1aT[DD * DD];           // [i][d] = W1[d*256 + i]
__device__ float g_W1bT[DD * DD];           // [i][d] = W1[d*256 + 128 + i]
__device__ float g_W2T[DD * DD];            // [k][e] = W2[e*128 + k]  (reduction-major)

#define ASTRIDE 132         // A-fragment LDS conflict-free
#define BSTRIDE 136         // B-fragment LDS conflict-free

// ---------------- smem layouts ----------------
struct SM2 {                // tf32 GEMM precompute kernel (T and C): 128 rows/task
    uint32_t b[DD * BSTRIDE];    // tf32 weights [k][n]
    uint32_t a[128 * ASTRIDE];   // tf32 gathered rows [r][k]
};
struct SK {                 // main kernel: 4 nodes (128 edge rows) per task
    uint32_t b[DD * BSTRIDE];    // tf32 W2T [k][n]
    uint32_t a[128 * ASTRIDE];   // tf32 h1  [r][k]
    float b2s[DD];
    float w3s[DD];
    float logit[128];
    float att[128];
    int   idx[128];
    int   nodeid[4];
    int   len[4];
};

__device__ __forceinline__ float wmaxf(float v) {
    #pragma unroll
    for (int o = 16; o; o >>= 1) v = fmaxf(v, __shfl_xor_sync(0xffffffffu, v, o));
    return v;
}
__device__ __forceinline__ float wsumf(float v) {
    #pragma unroll
    for (int o = 16; o; o >>= 1) v += __shfl_xor_sync(0xffffffffu, v, o);
    return v;
}
__device__ __forceinline__ uint32_t f2tf32(float f) {
    uint32_t r;
    asm("cvt.rna.tf32.f32 %0, %1;" : "=r"(r) : "f"(f));
    return r;
}
__device__ __forceinline__ void mma_tf32(float c[4],
                                         uint32_t a0, uint32_t a1, uint32_t a2, uint32_t a3,
                                         uint32_t b0, uint32_t b1) {
    asm volatile(
        "mma.sync.aligned.m16n8k8.row.col.f32.tf32.tf32.f32 "
        "{%0,%1,%2,%3}, {%4,%5,%6,%7}, {%8,%9}, {%0,%1,%2,%3};"
        : "+f"(c[0]), "+f"(c[1]), "+f"(c[2]), "+f"(c[3])
        : "r"(a0), "r"(a1), "r"(a2), "r"(a3), "r"(b0), "r"(b1));
}

// ---------------- K0: transpose weights into reduction-major global copies ----------------
__global__ void prep_kernel(const float* __restrict__ W1, const float* __restrict__ W2) {
    int t = blockIdx.x * blockDim.x + threadIdx.x;
    if (t < DD * DD) {
        int e = t & 127;     // output column
        int i = t >> 7;      // reduction index
        g_W1aT[t] = W1[e * 256 + i];
        g_W1bT[t] = W1[e * 256 + 128 + i];
        g_W2T[t]  = W2[e * 128 + i];
    }
}

// ---------------- K1/K2: tf32 tensor-core precompute of T (mode 0) / C (mode 1) ----------------
// Task-looped: B staged tf32 once per block; per task gather 128 rows, 16 warps
// tile C[128x128] as 16x64 warp tiles.
__global__ __launch_bounds__(512, 1)
void mlp_tc_kernel(const float* __restrict__ feats, const int* __restrict__ gather,
                   int nrows, const float* __restrict__ bias, int mode, int ntasks) {
    extern __shared__ unsigned char smem_raw[];
    SM2* s = reinterpret_cast<SM2*>(smem_raw);
    const float* __restrict__ WT = (mode == 0) ? g_W1aT : g_W1bT;
    float* __restrict__ out      = (mode == 0) ? g_T    : g_C;

    int t = threadIdx.x;
    int w = t >> 5, lane = t & 31;
    int grp = lane >> 2, tig = lane & 3;
    int rw = (w & 7) * 16;        // warp row block within 128
    int cw = (w >> 3) * 64;       // warp col block within 128

    for (int q = t; q < DD * DD; q += 512) {
        int k = q >> 7, n = q & 127;
        s->b[k * BSTRIDE + n] = f2tf32(WT[q]);
    }

    for (int task = blockIdx.x; task < ntasks; task += gridDim.x) {
        __syncthreads();   // previous MMA reads of s->a done before refill

        // fill a: 4 threads per row, each 32 contiguous floats
        {
            int r = t >> 2, q = t & 3;
            int row = task * 128 + r;
            bool ok = row < nrows;
            int rowid = ok ? (gather ? gather[row] : row) : 0;
            const float4* frow = reinterpret_cast<const float4*>(feats + (size_t)rowid * DD) + q * 8;
            uint4* dst = reinterpret_cast<uint4*>(s->a + r * ASTRIDE + q * 32);
            #pragma unroll
            for (int j = 0; j < 8; j++) {
                float4 v = ok ? frow[j] : make_float4(0.f, 0.f, 0.f, 0.f);
                uint4 o;
                o.x = f2tf32(v.x); o.y = f2tf32(v.y);
                o.z = f2tf32(v.z); o.w = f2tf32(v.w);
                dst[j] = o;
            }
        }
        __syncthreads();

        float acc[8][4];
        #pragma unroll
        for (int nt = 0; nt < 8; nt++)
            #pragma unroll
            for (int c = 0; c < 4; c++) acc[nt][c] = 0.f;

        #pragma unroll
        for (int k0 = 0; k0 < DD; k0 += 8) {
            const uint32_t* ar0 = s->a + (rw + grp) * ASTRIDE + k0 + tig;
            const uint32_t* ar1 = ar0 + 8 * ASTRIDE;
            uint32_t a0 = ar0[0];
            uint32_t a2 = ar0[4];
            uint32_t a1 = ar1[0];
            uint32_t a3 = ar1[4];
            const uint32_t* br0 = s->b + (k0 + tig) * BSTRIDE + cw + grp;
            const uint32_t* br1 = br0 + 4 * BSTRIDE;
            #pragma unroll
            for (int nt = 0; nt < 8; nt++) {
                mma_tf32(acc[nt], a0, a1, a2, a3, br0[nt * 8], br1[nt * 8]);
            }
        }

        // store: each lane owns rows {rw+grp, rw+grp+8}, cols c0..c0+1 per n-tile
        int row0 = task * 128 + rw + grp;
        int row1 = row0 + 8;
        #pragma unroll
        for (int nt = 0; nt < 8; nt++) {
            int c0 = cw + nt * 8 + tig * 2;
            float ba = bias ? bias[c0] : 0.f;
            float bb = bias ? bias[c0 + 1] : 0.f;
            if (row0 < nrows)
                *reinterpret_cast<float2*>(out + (size_t)row0 * DD + c0) =
                    make_float2(acc[nt][0] + ba, acc[nt][1] + bb);
            if (row1 < nrows)
                *reinterpret_cast<float2*>(out + (size_t)row1 * DD + c0) =
                    make_float2(acc[nt][2] + ba, acc[nt][3] + bb);
        }
    }
}

// ---------------- K3: task-looped, 4 nodes (128 rows) per task, 512 threads ----------------
__global__ __launch_bounds__(512, 1)
void graphrec_kernel(const float* __restrict__ u2e, const int* __restrict__ nodes,
                     const int* __restrict__ nidx, const int* __restrict__ nlen,
                     const float* __restrict__ b2, const float* __restrict__ W3,
                     const float* __restrict__ b3, float* __restrict__ out,
                     int ntasks) {
    extern __shared__ unsigned char smem_raw[];
    SK* s = reinterpret_cast<SK*>(smem_raw);
    int t = threadIdx.x;
    int w = t >> 5, lane = t & 31;
    int grp = lane >> 2, tig = lane & 3;
    int rw = (w & 7) * 16;        // warp row block within 128
    int cw = (w >> 3) * 64;       // warp col block within 128

    // ---- one-time per block: stage W2T (tf32), b2, W3 ----
    for (int q = t; q < DD * DD; q += 512) {
        int k = q >> 7, n = q & 127;
        s->b[k * BSTRIDE + n] = f2tf32(g_W2T[q]);
    }
    if (t < DD) { s->b2s[t] = b2[t]; s->w3s[t] = W3[t]; }
    float b3v = b3[0];

    for (int task = blockIdx.x; task < ntasks; task += gridDim.x) {
        __syncthreads();   // prev iteration's smem reads complete before overwrite

        if (t < 128) { s->idx[t] = nidx[task * 128 + t]; s->logit[t] = 0.f; }
        if (t < 4)   { s->nodeid[t] = nodes[task * 4 + t]; s->len[t] = nlen[task * 4 + t]; }
        __syncthreads();

        // ---- fill h1 (tf32): 4 threads per row, 32 contiguous floats each ----
        {
            int r = t >> 2, q = t & 3;
            int vrow = s->idx[r];
            int n = task * 4 + (r >> 5);
            const float4* trow = reinterpret_cast<const float4*>(g_T + (size_t)vrow * DD) + q * 8;
            const float4* crow = reinterpret_cast<const float4*>(g_C + (size_t)n * DD) + q * 8;
            uint4* dst = reinterpret_cast<uint4*>(s->a + r * ASTRIDE + q * 32);
            #pragma unroll
            for (int j = 0; j < 8; j++) {
                float4 tv = trow[j];
                float4 cv = crow[j];
                uint4 o;
                o.x = f2tf32(fmaxf(tv.x + cv.x, 0.f));
                o.y = f2tf32(fmaxf(tv.y + cv.y, 0.f));
                o.z = f2tf32(fmaxf(tv.z + cv.z, 0.f));
                o.w = f2tf32(fmaxf(tv.w + cv.w, 0.f));
                dst[j] = o;
            }
        }
        __syncthreads();

        // ---- tensor-core mainloop: 16 k-steps x 8 n-tiles of m16n8k8 ----
        float acc[8][4];
        #pragma unroll
        for (int nt = 0; nt < 8; nt++)
            #pragma unroll
            for (int c = 0; c < 4; c++) acc[nt][c] = 0.f;

        #pragma unroll
        for (int k0 = 0; k0 < DD; k0 += 8) {
            const uint32_t* ar0 = s->a + (rw + grp) * ASTRIDE + k0 + tig;
            const uint32_t* ar1 = ar0 + 8 * ASTRIDE;
            uint32_t a0 = ar0[0];
            uint32_t a2 = ar0[4];
            uint32_t a1 = ar1[0];
            uint32_t a3 = ar1[4];
            const uint32_t* br0 = s->b + (k0 + tig) * BSTRIDE + cw + grp;
            const uint32_t* br1 = br0 + 4 * BSTRIDE;
            #pragma unroll
            for (int nt = 0; nt < 8; nt++) {
                mma_tf32(acc[nt], a0, a1, a2, a3, br0[nt * 8], br1[nt * 8]);
            }
        }

        // ---- epilogue: h2 = relu(c + b2), partial logit = sum W3*h2 ----
        float pl0 = 0.f, pl1 = 0.f;
        #pragma unroll
        for (int nt = 0; nt < 8; nt++) {
            int c0 = cw + nt * 8 + tig * 2;
            float b2a = s->b2s[c0],     b2b = s->b2s[c0 + 1];
            float w3a = s->w3s[c0],     w3b = s->w3s[c0 + 1];
            pl0 = fmaf(w3a, fmaxf(acc[nt][0] + b2a, 0.f), pl0);
            pl0 = fmaf(w3b, fmaxf(acc[nt][1] + b2b, 0.f), pl0);
            pl1 = fmaf(w3a, fmaxf(acc[nt][2] + b2a, 0.f), pl1);
            pl1 = fmaf(w3b, fmaxf(acc[nt][3] + b2b, 0.f), pl1);
        }
        pl0 += __shfl_xor_sync(0xffffffffu, pl0, 1);
        pl0 += __shfl_xor_sync(0xffffffffu, pl0, 2);
        pl1 += __shfl_xor_sync(0xffffffffu, pl1, 1);
        pl1 += __shfl_xor_sync(0xffffffffu, pl1, 2);
        if (tig == 0) {
            atomicAdd(&s->logit[rw + grp],     pl0);
            atomicAdd(&s->logit[rw + grp + 8], pl1);
        }
        __syncthreads();

        // ---- masked softmax over K, one warp per node (4 nodes) ----
        if (w < 4) {
            int nn = w;
            int len = s->len[nn];
            float lg = s->logit[nn * KK + lane] + b3v;
            bool valid = lane < len;
            float v = valid ? lg : -3.0e38f;
            float m = wmaxf(v);
            float ex = valid ? expf(lg - m) : 0.f;
            float sm = wsumf(ex);
            s->att[nn * KK + lane] = (len > 0) ? (ex / sm) : 0.f;
        }
        __syncthreads();

        // ---- aggregation + output (exact fp32): thread -> (node nn, dim d) ----
        {
            int nn = t >> 7;
            int d  = t & 127;
            int n = task * 4 + nn;
            float self = u2e[(size_t)s->nodeid[nn] * DD + d];
            float o;
            if (s->len[nn] > 0) {
                float agg = 0.f;
                #pragma unroll
                for (int k = 0; k < KK; k++)
                    agg = fmaf(s->att[nn * KK + k], u2e[(size_t)s->idx[nn * KK + k] * DD + d], agg);
                o = 0.5f * (agg + self);
            } else {
                o = self;
            }
            out[(size_t)n * DD + d] = o;
        }
    }
}

// ---------------- launcher ----------------
extern "C" void kernel_launch(void* const* d_in, const int* in_sizes, int n_in,
                              void* d_out, int out_size) {
    const int*   nodes = (const int*)d_in[0];
    const int*   nidx  = (const int*)d_in[1];
    const int*   nlen  = (const int*)d_in[2];
    const float* u2e   = (const float*)d_in[3];
    const float* W1    = (const float*)d_in[4];
    const float* b1    = (const float*)d_in[5];
    const float* W2    = (const float*)d_in[6];
    const float* b2    = (const float*)d_in[7];
    const float* W3    = (const float*)d_in[8];
    const float* b3    = (const float*)d_in[9];
    float* out = (float*)d_out;

    cudaFuncSetAttribute(mlp_tc_kernel,  cudaFuncAttributeMaxDynamicSharedMemorySize, (int)sizeof(SM2));
    cudaFuncSetAttribute(graphrec_kernel, cudaFuncAttributeMaxDynamicSharedMemorySize, (int)sizeof(SK));

    const int SMS = 152;   // GB300: 152 SMs, one resident block each (smem-bound)
    int tasksT = (VOCAB + 127) / 128;
    int tasksC = (NN + 127) / 128;
    int tasksG = NN / 4;
    int gT = tasksT < SMS ? tasksT : SMS;
    int gC = tasksC < SMS ? tasksC : SMS;
    int gG = tasksG < SMS ? tasksG : SMS;

    prep_kernel<<<(DD * DD + 255) / 256, 256>>>(W1, W2);
    mlp_tc_kernel<<<gT, 512, sizeof(SM2)>>>(u2e, nullptr, VOCAB, nullptr, 0, tasksT);
    mlp_tc_kernel<<<gC, 512, sizeof(SM2)>>>(u2e, nodes, NN, b1, 1, tasksC);
    graphrec_kernel<<<gG, 512, sizeof(SK)>>>(u2e, nodes, nidx, nlen, b2, W3, b3, out, tasksG);
}

// round 10
// speedup vs baseline: 1.9231x; 1.0611x over previous
#include <cuda_runtime.h>
#include <math.h>
#include <stdint.h>

#define NN    20000
#define KK    32
#define DD    128
#define VOCAB 100000

// ---------------- scratch (static device globals: allocation-free) ----------------
__device__ float g_T[(size_t)VOCAB * DD];   // T[v][d] = sum_i u2e[v][i] * W1[d, i]
__device__ float g_C[(size_t)NN * DD];      // C[n][d] = b1[d] + sum_i self[i] * W1[d, 128+i]
__device__ float g_W1aT[DD * DD];           // [i][d] = W1[d*256 + i]
__device__ float g_W1bT[DD * DD];           // [i][d] = W1[d*256 + 128 + i]
__device__ float g_W2T[DD * DD];            // [k][e] = W2[e*128 + k]  (reduction-major)

#define ASTRIDE 132         // A-fragment LDS conflict-free
#define BSTRIDE 136         // B-fragment LDS conflict-free

// ---------------- smem layouts ----------------
struct SM3 {                // merged T/C precompute: 2 groups x 64 rows, both weight mats
    uint32_t b[2][DD * BSTRIDE];    // tf32 W1aT / W1bT
    uint32_t a[2][64 * ASTRIDE];    // per-group gathered rows
};
struct SK2 {                // main kernel: 2 groups x (2 nodes = 64 edge rows)
    uint32_t b[DD * BSTRIDE];       // tf32 W2T (shared by both groups)
    uint32_t a[2][64 * ASTRIDE];    // per-group tf32 h1
    float b2s[DD];
    float w3s[DD];
    float logit[2][64];
    float att[2][64];
    int   idx[2][64];
    int   nodeid[2][2];
    int   len[2][2];
};

__device__ __forceinline__ void gsync(int g) {      // group barrier: 8 warps = 256 threads
    asm volatile("bar.sync %0, 256;" :: "r"(g + 1) : "memory");
}
__device__ __forceinline__ float wmaxf(float v) {
    #pragma unroll
    for (int o = 16; o; o >>= 1) v = fmaxf(v, __shfl_xor_sync(0xffffffffu, v, o));
    return v;
}
__device__ __forceinline__ float wsumf(float v) {
    #pragma unroll
    for (int o = 16; o; o >>= 1) v += __shfl_xor_sync(0xffffffffu, v, o);
    return v;
}
__device__ __forceinline__ uint32_t f2tf32(float f) {
    uint32_t r;
    asm("cvt.rna.tf32.f32 %0, %1;" : "=r"(r) : "f"(f));
    return r;
}
__device__ __forceinline__ void mma_tf32(float c[4],
                                         uint32_t a0, uint32_t a1, uint32_t a2, uint32_t a3,
                                         uint32_t b0, uint32_t b1) {
    asm volatile(
        "mma.sync.aligned.m16n8k8.row.col.f32.tf32.tf32.f32 "
        "{%0,%1,%2,%3}, {%4,%5,%6,%7}, {%8,%9}, {%0,%1,%2,%3};"
        : "+f"(c[0]), "+f"(c[1]), "+f"(c[2]), "+f"(c[3])
        : "r"(a0), "r"(a1), "r"(a2), "r"(a3), "r"(b0), "r"(b1));
}

// ---------------- K0: transpose weights into reduction-major global copies ----------------
__global__ void prep_kernel(const float* __restrict__ W1, const float* __restrict__ W2) {
    int t = blockIdx.x * blockDim.x + threadIdx.x;
    if (t < DD * DD) {
        int e = t & 127;     // output column
        int i = t >> 7;      // reduction index
        g_W1aT[t] = W1[e * 256 + i];
        g_W1bT[t] = W1[e * 256 + 128 + i];
        g_W2T[t]  = W2[e * 128 + i];
    }
}

// ---------------- K1: merged tf32 precompute of T and C, 2 warp-groups per block ----------------
// Task pool: [0, tasksT) -> T rows (identity gather), [tasksT, tasksAll) -> C rows (nodes gather).
// Each group: 8 warps, 64 rows x 128 cols, warp tiles 16x64.
__global__ __launch_bounds__(512, 1)
void mlp_tc2_kernel(const float* __restrict__ u2e, const int* __restrict__ nodes,
                    const float* __restrict__ b1, int tasksT, int tasksAll) {
    extern __shared__ unsigned char smem_raw[];
    SM3* s = reinterpret_cast<SM3*>(smem_raw);
    int t = threadIdx.x;
    int w = t >> 5, lane = t & 31;
    int grp = lane >> 2, tig = lane & 3;
    int g = w >> 3, wg = w & 7, tg = t & 255;
    int rw = (wg & 3) * 16;        // warp row block within 64
    int cw = (wg >> 2) * 64;       // warp col block within 128

    for (int q = t; q < DD * DD; q += 512) {
        int k = q >> 7, n = q & 127;
        s->b[0][k * BSTRIDE + n] = f2tf32(g_W1aT[q]);
        s->b[1][k * BSTRIDE + n] = f2tf32(g_W1bT[q]);
    }
    __syncthreads();

    for (int task = blockIdx.x * 2 + g; task < tasksAll; task += gridDim.x * 2) {
        gsync(g);   // previous MMA reads of s->a[g] done before refill

        int isC   = task >= tasksT;
        int taskL = isC ? task - tasksT : task;
        int nrows = isC ? NN : VOCAB;

        // fill a[g]: 4 threads per row, each 32 contiguous floats
        {
            int r = tg >> 2, q = tg & 3;
            int row = taskL * 64 + r;
            bool ok = row < nrows;
            int rowid = ok ? (isC ? nodes[row] : row) : 0;
            const float4* frow = reinterpret_cast<const float4*>(u2e + (size_t)rowid * DD) + q * 8;
            uint4* dst = reinterpret_cast<uint4*>(s->a[g] + r * ASTRIDE + q * 32);
            #pragma unroll
            for (int j = 0; j < 8; j++) {
                float4 v = ok ? frow[j] : make_float4(0.f, 0.f, 0.f, 0.f);
                uint4 o;
                o.x = f2tf32(v.x); o.y = f2tf32(v.y);
                o.z = f2tf32(v.z); o.w = f2tf32(v.w);
                dst[j] = o;
            }
        }
        gsync(g);

        const uint32_t* __restrict__ B = s->b[isC];
        float acc[8][4];
        #pragma unroll
        for (int nt = 0; nt < 8; nt++)
            #pragma unroll
            for (int c = 0; c < 4; c++) acc[nt][c] = 0.f;

        #pragma unroll
        for (int k0 = 0; k0 < DD; k0 += 8) {
            const uint32_t* ar0 = s->a[g] + (rw + grp) * ASTRIDE + k0 + tig;
            const uint32_t* ar1 = ar0 + 8 * ASTRIDE;
            uint32_t a0 = ar0[0];
            uint32_t a2 = ar0[4];
            uint32_t a1 = ar1[0];
            uint32_t a3 = ar1[4];
            const uint32_t* br0 = B + (k0 + tig) * BSTRIDE + cw + grp;
            const uint32_t* br1 = br0 + 4 * BSTRIDE;
            #pragma unroll
            for (int nt = 0; nt < 8; nt++) {
                mma_tf32(acc[nt], a0, a1, a2, a3, br0[nt * 8], br1[nt * 8]);
            }
        }

        float* __restrict__ out = isC ? g_C : g_T;
        int row0 = taskL * 64 + rw + grp;
        int row1 = row0 + 8;
        #pragma unroll
        for (int nt = 0; nt < 8; nt++) {
            int c0 = cw + nt * 8 + tig * 2;
            float ba = isC ? b1[c0] : 0.f;
            float bb = isC ? b1[c0 + 1] : 0.f;
            if (row0 < nrows)
                *reinterpret_cast<float2*>(out + (size_t)row0 * DD + c0) =
                    make_float2(acc[nt][0] + ba, acc[nt][1] + bb);
            if (row1 < nrows)
                *reinterpret_cast<float2*>(out + (size_t)row1 * DD + c0) =
                    make_float2(acc[nt][2] + ba, acc[nt][3] + bb);
        }
    }
}

// ---------------- K3: 2 warp-groups per block, each 2 nodes (64 rows) per task ----------------
__global__ __launch_bounds__(512, 1)
void graphrec_kernel(const float* __restrict__ u2e, const int* __restrict__ nodes,
                     const int* __restrict__ nidx, const int* __restrict__ nlen,
                     const float* __restrict__ b2, const float* __restrict__ W3,
                     const float* __restrict__ b3, float* __restrict__ out,
                     int ntasks) {
    extern __shared__ unsigned char smem_raw[];
    SK2* s = reinterpret_cast<SK2*>(smem_raw);
    int t = threadIdx.x;
    int w = t >> 5, lane = t & 31;
    int grp = lane >> 2, tig = lane & 3;
    int g = w >> 3, wg = w & 7, tg = t & 255;
    int rw = (wg & 3) * 16;        // warp row block within 64
    int cw = (wg >> 2) * 64;       // warp col block within 128

    // ---- one-time per block: stage W2T (tf32), b2, W3 ----
    for (int q = t; q < DD * DD; q += 512) {
        int k = q >> 7, n = q & 127;
        s->b[k * BSTRIDE + n] = f2tf32(g_W2T[q]);
    }
    if (t < DD) { s->b2s[t] = b2[t]; s->w3s[t] = W3[t]; }
    float b3v = b3[0];
    __syncthreads();

    for (int task = blockIdx.x * 2 + g; task < ntasks; task += gridDim.x * 2) {
        gsync(g);   // prev iteration's reads of this group's smem complete

        if (tg < 64) { s->idx[g][tg] = nidx[task * 64 + tg]; s->logit[g][tg] = 0.f; }
        if (tg < 2)  { s->nodeid[g][tg] = nodes[task * 2 + tg]; s->len[g][tg] = nlen[task * 2 + tg]; }
        gsync(g);

        // ---- fill h1 (tf32): 4 threads per row, 32 contiguous floats each ----
        {
            int r = tg >> 2, q = tg & 3;
            int vrow = s->idx[g][r];
            int n = task * 2 + (r >> 5);
            const float4* trow = reinterpret_cast<const float4*>(g_T + (size_t)vrow * DD) + q * 8;
            const float4* crow = reinterpret_cast<const float4*>(g_C + (size_t)n * DD) + q * 8;
            uint4* dst = reinterpret_cast<uint4*>(s->a[g] + r * ASTRIDE + q * 32);
            #pragma unroll
            for (int j = 0; j < 8; j++) {
                float4 tv = trow[j];
                float4 cv = crow[j];
                uint4 o;
                o.x = f2tf32(fmaxf(tv.x + cv.x, 0.f));
                o.y = f2tf32(fmaxf(tv.y + cv.y, 0.f));
                o.z = f2tf32(fmaxf(tv.z + cv.z, 0.f));
                o.w = f2tf32(fmaxf(tv.w + cv.w, 0.f));
                dst[j] = o;
            }
        }
        gsync(g);

        // ---- tensor-core mainloop: 16 k-steps x 8 n-tiles of m16n8k8 ----
        float acc[8][4];
        #pragma unroll
        for (int nt = 0; nt < 8; nt++)
            #pragma unroll
            for (int c = 0; c < 4; c++) acc[nt][c] = 0.f;

        #pragma unroll
        for (int k0 = 0; k0 < DD; k0 += 8) {
            const uint32_t* ar0 = s->a[g] + (rw + grp) * ASTRIDE + k0 + tig;
            const uint32_t* ar1 = ar0 + 8 * ASTRIDE;
            uint32_t a0 = ar0[0];
            uint32_t a2 = ar0[4];
            uint32_t a1 = ar1[0];
            uint32_t a3 = ar1[4];
            const uint32_t* br0 = s->b + (k0 + tig) * BSTRIDE + cw + grp;
            const uint32_t* br1 = br0 + 4 * BSTRIDE;
            #pragma unroll
            for (int nt = 0; nt < 8; nt++) {
                mma_tf32(acc[nt], a0, a1, a2, a3, br0[nt * 8], br1[nt * 8]);
            }
        }

        // ---- epilogue: h2 = relu(c + b2), partial logit = sum W3*h2 ----
        float pl0 = 0.f, pl1 = 0.f;
        #pragma unroll
        for (int nt = 0; nt < 8; nt++) {
            int c0 = cw + nt * 8 + tig * 2;
            float b2a = s->b2s[c0],     b2b = s->b2s[c0 + 1];
            float w3a = s->w3s[c0],     w3b = s->w3s[c0 + 1];
            pl0 = fmaf(w3a, fmaxf(acc[nt][0] + b2a, 0.f), pl0);
            pl0 = fmaf(w3b, fmaxf(acc[nt][1] + b2b, 0.f), pl0);
            pl1 = fmaf(w3a, fmaxf(acc[nt][2] + b2a, 0.f), pl1);
            pl1 = fmaf(w3b, fmaxf(acc[nt][3] + b2b, 0.f), pl1);
        }
        pl0 += __shfl_xor_sync(0xffffffffu, pl0, 1);
        pl0 += __shfl_xor_sync(0xffffffffu, pl0, 2);
        pl1 += __shfl_xor_sync(0xffffffffu, pl1, 1);
        pl1 += __shfl_xor_sync(0xffffffffu, pl1, 2);
        if (tig == 0) {
            atomicAdd(&s->logit[g][rw + grp],     pl0);
            atomicAdd(&s->logit[g][rw + grp + 8], pl1);
        }
        gsync(g);

        // ---- masked softmax over K, one warp per node (2 nodes/group) ----
        if (wg < 2) {
            int nn = wg;
            int len = s->len[g][nn];
            float lg = s->logit[g][nn * KK + lane] + b3v;
            bool valid = lane < len;
            float v = valid ? lg : -3.0e38f;
            float m = wmaxf(v);
            float ex = valid ? expf(lg - m) : 0.f;
            float sm = wsumf(ex);
            s->att[g][nn * KK + lane] = (len > 0) ? (ex / sm) : 0.f;
        }
        gsync(g);

        // ---- aggregation + output (exact fp32): thread -> (node nn, dim d) ----
        {
            int nn = tg >> 7;
            int d  = tg & 127;
            int n = task * 2 + nn;
            float self = u2e[(size_t)s->nodeid[g][nn] * DD + d];
            float o;
            if (s->len[g][nn] > 0) {
                float agg = 0.f;
                #pragma unroll
                for (int k = 0; k < KK; k++)
                    agg = fmaf(s->att[g][nn * KK + k],
                               u2e[(size_t)s->idx[g][nn * KK + k] * DD + d], agg);
                o = 0.5f * (agg + self);
            } else {
                o = self;
            }
            out[(size_t)n * DD + d] = o;
        }
    }
}

// ---------------- launcher ----------------
extern "C" void kernel_launch(void* const* d_in, const int* in_sizes, int n_in,
                              void* d_out, int out_size) {
    const int*   nodes = (const int*)d_in[0];
    const int*   nidx  = (const int*)d_in[1];
    const int*   nlen  = (const int*)d_in[2];
    const float* u2e   = (const float*)d_in[3];
    const float* W1    = (const float*)d_in[4];
    const float* b1    = (const float*)d_in[5];
    const float* W2    = (const float*)d_in[6];
    const float* b2    = (const float*)d_in[7];
    const float* W3    = (const float*)d_in[8];
    const float* b3    = (const float*)d_in[9];
    float* out = (float*)d_out;

    cudaFuncSetAttribute(mlp_tc2_kernel,  cudaFuncAttributeMaxDynamicSharedMemorySize, (int)sizeof(SM3));
    cudaFuncSetAttribute(graphrec_kernel, cudaFuncAttributeMaxDynamicSharedMemorySize, (int)sizeof(SK2));

    const int SMS = 152;   // GB300: 152 SMs, one resident block each (smem-bound)
    int tasksT   = (VOCAB + 63) / 64;          // 1563
    int tasksC   = (NN + 63) / 64;             // 313
    int tasksAll = tasksT + tasksC;            // 1876
    int tasksG   = NN / 2;                     // 10000

    int gM = (tasksAll + 1) / 2; if (gM > SMS) gM = SMS;
    int gG = (tasksG + 1) / 2;   if (gG > SMS) gG = SMS;

    prep_kernel<<<(DD * DD + 255) / 256, 256>>>(W1, W2);
    mlp_tc2_kernel<<<gM, 512, sizeof(SM3)>>>(u2e, nodes, b1, tasksT, tasksAll);
    graphrec_kernel<<<gG, 512, sizeof(SK2)>>>(u2e, nodes, nidx, nlen, b2, W3, b3, out, tasksG);
}

// round 11
// speedup vs baseline: 2.0285x; 1.0548x over previous
#include <cuda_runtime.h>
#include <math.h>
#include <stdint.h>

#define NN    20000
#define KK    32
#define DD    128
#define VOCAB 100000

// ---------------- scratch (static device globals: allocation-free) ----------------
__device__ float g_T[(size_t)VOCAB * DD];   // T[v][d] = sum_i u2e[v][i] * W1[d, i]
__device__ float g_C[(size_t)NN * DD];      // C[n][d] = b1[d] + sum_i self[i] * W1[d, 128+i]
__device__ float g_W1aT[DD * DD];           // [i][d] = W1[d*256 + i]
__device__ float g_W1bT[DD * DD];           // [i][d] = W1[d*256 + 128 + i]
__device__ float g_W2T[DD * DD];            // [k][e] = W2[e*128 + k]  (reduction-major)

#define ASTRIDE 132         // A-fragment LDS conflict-free
#define BSTRIDE 136         // B-fragment LDS conflict-free

// ---------------- smem layouts ----------------
struct SM3 {                // merged T/C precompute: 2 groups x 64 rows, both weight mats
    uint32_t b[2][DD * BSTRIDE];    // tf32 W1aT / W1bT
    uint32_t a[2][64 * ASTRIDE];    // per-group gathered rows
};
struct SK4 {                // main kernel: 4 groups x (1 node = 32 edge rows)
    uint32_t b[DD * BSTRIDE];       // tf32 W2T (shared by all groups)
    uint32_t a[4][32 * ASTRIDE];    // per-group tf32 h1
    float b2s[DD];
    float w3s[DD];
    float logit[4][32];
    float att[4][32];
    int   idx[4][32];
};

__device__ __forceinline__ void gsync2(int g) {     // 8-warp group barrier (mlp kernel)
    asm volatile("bar.sync %0, 256;" :: "r"(g + 1) : "memory");
}
__device__ __forceinline__ void gsync4(int g) {     // 4-warp group barrier (graphrec)
    asm volatile("bar.sync %0, 128;" :: "r"(g + 1) : "memory");
}
__device__ __forceinline__ float wmaxf(float v) {
    #pragma unroll
    for (int o = 16; o; o >>= 1) v = fmaxf(v, __shfl_xor_sync(0xffffffffu, v, o));
    return v;
}
__device__ __forceinline__ float wsumf(float v) {
    #pragma unroll
    for (int o = 16; o; o >>= 1) v += __shfl_xor_sync(0xffffffffu, v, o);
    return v;
}
__device__ __forceinline__ uint32_t f2tf32(float f) {
    uint32_t r;
    asm("cvt.rna.tf32.f32 %0, %1;" : "=r"(r) : "f"(f));
    return r;
}
__device__ __forceinline__ void mma_tf32(float c[4],
                                         uint32_t a0, uint32_t a1, uint32_t a2, uint32_t a3,
                                         uint32_t b0, uint32_t b1) {
    asm volatile(
        "mma.sync.aligned.m16n8k8.row.col.f32.tf32.tf32.f32 "
        "{%0,%1,%2,%3}, {%4,%5,%6,%7}, {%8,%9}, {%0,%1,%2,%3};"
        : "+f"(c[0]), "+f"(c[1]), "+f"(c[2]), "+f"(c[3])
        : "r"(a0), "r"(a1), "r"(a2), "r"(a3), "r"(b0), "r"(b1));
}

// ---------------- K0: transpose weights into reduction-major global copies ----------------
__global__ void prep_kernel(const float* __restrict__ W1, const float* __restrict__ W2) {
    int t = blockIdx.x * blockDim.x + threadIdx.x;
    if (t < DD * DD) {
        int e = t & 127;     // output column
        int i = t >> 7;      // reduction index
        g_W1aT[t] = W1[e * 256 + i];
        g_W1bT[t] = W1[e * 256 + 128 + i];
        g_W2T[t]  = W2[e * 128 + i];
    }
}

// ---------------- K1: merged tf32 precompute of T and C, 2 warp-groups per block ----------------
__global__ __launch_bounds__(512, 1)
void mlp_tc2_kernel(const float* __restrict__ u2e, const int* __restrict__ nodes,
                    const float* __restrict__ b1, int tasksT, int tasksAll) {
    extern __shared__ unsigned char smem_raw[];
    SM3* s = reinterpret_cast<SM3*>(smem_raw);
    int t = threadIdx.x;
    int w = t >> 5, lane = t & 31;
    int grp = lane >> 2, tig = lane & 3;
    int g = w >> 3, wg = w & 7, tg = t & 255;
    int rw = (wg & 3) * 16;        // warp row block within 64
    int cw = (wg >> 2) * 64;       // warp col block within 128

    for (int q = t; q < DD * DD; q += 512) {
        int k = q >> 7, n = q & 127;
        s->b[0][k * BSTRIDE + n] = f2tf32(g_W1aT[q]);
        s->b[1][k * BSTRIDE + n] = f2tf32(g_W1bT[q]);
    }
    __syncthreads();

    for (int task = blockIdx.x * 2 + g; task < tasksAll; task += gridDim.x * 2) {
        gsync2(g);   // previous MMA reads of s->a[g] done before refill

        int isC   = task >= tasksT;
        int taskL = isC ? task - tasksT : task;
        int nrows = isC ? NN : VOCAB;

        // fill a[g]: 4 threads per row, each 32 contiguous floats
        {
            int r = tg >> 2, q = tg & 3;
            int row = taskL * 64 + r;
            bool ok = row < nrows;
            int rowid = ok ? (isC ? nodes[row] : row) : 0;
            const float4* frow = reinterpret_cast<const float4*>(u2e + (size_t)rowid * DD) + q * 8;
            uint4* dst = reinterpret_cast<uint4*>(s->a[g] + r * ASTRIDE + q * 32);
            #pragma unroll
            for (int j = 0; j < 8; j++) {
                float4 v = ok ? frow[j] : make_float4(0.f, 0.f, 0.f, 0.f);
                uint4 o;
                o.x = f2tf32(v.x); o.y = f2tf32(v.y);
                o.z = f2tf32(v.z); o.w = f2tf32(v.w);
                dst[j] = o;
            }
        }
        gsync2(g);

        const uint32_t* __restrict__ B = s->b[isC];
        float acc[8][4];
        #pragma unroll
        for (int nt = 0; nt < 8; nt++)
            #pragma unroll
            for (int c = 0; c < 4; c++) acc[nt][c] = 0.f;

        #pragma unroll
        for (int k0 = 0; k0 < DD; k0 += 8) {
            const uint32_t* ar0 = s->a[g] + (rw + grp) * ASTRIDE + k0 + tig;
            const uint32_t* ar1 = ar0 + 8 * ASTRIDE;
            uint32_t a0 = ar0[0];
            uint32_t a2 = ar0[4];
            uint32_t a1 = ar1[0];
            uint32_t a3 = ar1[4];
            const uint32_t* br0 = B + (k0 + tig) * BSTRIDE + cw + grp;
            const uint32_t* br1 = br0 + 4 * BSTRIDE;
            #pragma unroll
            for (int nt = 0; nt < 8; nt++) {
                mma_tf32(acc[nt], a0, a1, a2, a3, br0[nt * 8], br1[nt * 8]);
            }
        }

        float* __restrict__ out = isC ? g_C : g_T;
        int row0 = taskL * 64 + rw + grp;
        int row1 = row0 + 8;
        #pragma unroll
        for (int nt = 0; nt < 8; nt++) {
            int c0 = cw + nt * 8 + tig * 2;
            float ba = isC ? b1[c0] : 0.f;
            float bb = isC ? b1[c0 + 1] : 0.f;
            if (row0 < nrows)
                *reinterpret_cast<float2*>(out + (size_t)row0 * DD + c0) =
                    make_float2(acc[nt][0] + ba, acc[nt][1] + bb);
            if (row1 < nrows)
                *reinterpret_cast<float2*>(out + (size_t)row1 * DD + c0) =
                    make_float2(acc[nt][2] + ba, acc[nt][3] + bb);
        }
    }
}

// ---------------- K3: 4 warp-groups per block, 1 node (32 rows) per task ----------------
__global__ __launch_bounds__(512, 1)
void graphrec_kernel(const float* __restrict__ u2e, const int* __restrict__ nodes,
                     const int* __restrict__ nidx, const int* __restrict__ nlen,
                     const float* __restrict__ b2, const float* __restrict__ W3,
                     const float* __restrict__ b3, float* __restrict__ out,
                     int ntasks) {
    extern __shared__ unsigned char smem_raw[];
    SK4* s = reinterpret_cast<SK4*>(smem_raw);
    int t = threadIdx.x;
    int w = t >> 5, lane = t & 31;
    int grp = lane >> 2, tig = lane & 3;
    int g = w >> 2, wg = w & 3, tg = t & 127;
    int rw = (wg & 1) * 16;        // warp row block within 32
    int cw = (wg >> 1) * 64;       // warp col block within 128

    // ---- one-time per block: stage W2T (tf32), b2, W3 ----
    for (int q = t; q < DD * DD; q += 512) {
        int k = q >> 7, n = q & 127;
        s->b[k * BSTRIDE + n] = f2tf32(g_W2T[q]);
    }
    if (t < DD) { s->b2s[t] = b2[t]; s->w3s[t] = W3[t]; }
    float b3v = b3[0];
    __syncthreads();

    for (int task = blockIdx.x * 4 + g; task < ntasks; task += gridDim.x * 4) {
        gsync4(g);   // prev iteration's reads of this group's smem complete

        // ---- fill h1 (tf32): 4 threads per row, 32 contiguous floats each.
        //      idx staged to smem and logit zeroed in the same phase (no extra barrier).
        {
            int r = tg >> 2, q = tg & 3;
            int vrow = nidx[task * KK + r];           // 4-way uniform -> broadcast
            if (tg < KK) { s->idx[g][tg] = nidx[task * KK + tg]; s->logit[g][tg] = 0.f; }
            const float4* trow = reinterpret_cast<const float4*>(g_T + (size_t)vrow * DD) + q * 8;
            const float4* crow = reinterpret_cast<const float4*>(g_C + (size_t)task * DD) + q * 8;
            uint4* dst = reinterpret_cast<uint4*>(s->a[g] + r * ASTRIDE + q * 32);
            #pragma unroll
            for (int j = 0; j < 8; j++) {
                float4 tv = trow[j];
                float4 cv = crow[j];
                uint4 o;
                o.x = f2tf32(fmaxf(tv.x + cv.x, 0.f));
                o.y = f2tf32(fmaxf(tv.y + cv.y, 0.f));
                o.z = f2tf32(fmaxf(tv.z + cv.z, 0.f));
                o.w = f2tf32(fmaxf(tv.w + cv.w, 0.f));
                dst[j] = o;
            }
        }
        gsync4(g);

        // ---- tensor-core mainloop: 16 k-steps x 8 n-tiles of m16n8k8 ----
        float acc[8][4];
        #pragma unroll
        for (int nt = 0; nt < 8; nt++)
            #pragma unroll
            for (int c = 0; c < 4; c++) acc[nt][c] = 0.f;

        #pragma unroll
        for (int k0 = 0; k0 < DD; k0 += 8) {
            const uint32_t* ar0 = s->a[g] + (rw + grp) * ASTRIDE + k0 + tig;
            const uint32_t* ar1 = ar0 + 8 * ASTRIDE;
            uint32_t a0 = ar0[0];
            uint32_t a2 = ar0[4];
            uint32_t a1 = ar1[0];
            uint32_t a3 = ar1[4];
            const uint32_t* br0 = s->b + (k0 + tig) * BSTRIDE + cw + grp;
            const uint32_t* br1 = br0 + 4 * BSTRIDE;
            #pragma unroll
            for (int nt = 0; nt < 8; nt++) {
                mma_tf32(acc[nt], a0, a1, a2, a3, br0[nt * 8], br1[nt * 8]);
            }
        }

        // ---- epilogue: h2 = relu(c + b2), partial logit = sum W3*h2 ----
        float pl0 = 0.f, pl1 = 0.f;
        #pragma unroll
        for (int nt = 0; nt < 8; nt++) {
            int c0 = cw + nt * 8 + tig * 2;
            float b2a = s->b2s[c0],     b2b = s->b2s[c0 + 1];
            float w3a = s->w3s[c0],     w3b = s->w3s[c0 + 1];
            pl0 = fmaf(w3a, fmaxf(acc[nt][0] + b2a, 0.f), pl0);
            pl0 = fmaf(w3b, fmaxf(acc[nt][1] + b2b, 0.f), pl0);
            pl1 = fmaf(w3a, fmaxf(acc[nt][2] + b2a, 0.f), pl1);
            pl1 = fmaf(w3b, fmaxf(acc[nt][3] + b2b, 0.f), pl1);
        }
        pl0 += __shfl_xor_sync(0xffffffffu, pl0, 1);
        pl0 += __shfl_xor_sync(0xffffffffu, pl0, 2);
        pl1 += __shfl_xor_sync(0xffffffffu, pl1, 1);
        pl1 += __shfl_xor_sync(0xffffffffu, pl1, 2);
        if (tig == 0) {
            atomicAdd(&s->logit[g][rw + grp],     pl0);
            atomicAdd(&s->logit[g][rw + grp + 8], pl1);
        }
        gsync4(g);

        // ---- masked softmax over K, warp 0 of the group ----
        if (wg == 0) {
            int len = nlen[task];
            float lg = s->logit[g][lane] + b3v;
            bool valid = lane < len;
            float v = valid ? lg : -3.0e38f;
            float m = wmaxf(v);
            float ex = valid ? expf(lg - m) : 0.f;
            float sm = wsumf(ex);
            s->att[g][lane] = (len > 0) ? (ex / sm) : 0.f;
        }
        gsync4(g);

        // ---- aggregation + output (exact fp32): thread tg -> dim d ----
        {
            int d = tg;
            float self = u2e[(size_t)nodes[task] * DD + d];
            float o;
            if (nlen[task] > 0) {
                float agg = 0.f;
                #pragma unroll
                for (int k = 0; k < KK; k++)
                    agg = fmaf(s->att[g][k],
                               u2e[(size_t)s->idx[g][k] * DD + d], agg);
                o = 0.5f * (agg + self);
            } else {
                o = self;
            }
            out[(size_t)task * DD + d] = o;
        }
    }
}

// ---------------- launcher ----------------
extern "C" void kernel_launch(void* const* d_in, const int* in_sizes, int n_in,
                              void* d_out, int out_size) {
    const int*   nodes = (const int*)d_in[0];
    const int*   nidx  = (const int*)d_in[1];
    const int*   nlen  = (const int*)d_in[2];
    const float* u2e   = (const float*)d_in[3];
    const float* W1    = (const float*)d_in[4];
    const float* b1    = (const float*)d_in[5];
    const float* W2    = (const float*)d_in[6];
    const float* b2    = (const float*)d_in[7];
    const float* W3    = (const float*)d_in[8];
    const float* b3    = (const float*)d_in[9];
    float* out = (float*)d_out;

    cudaFuncSetAttribute(mlp_tc2_kernel,  cudaFuncAttributeMaxDynamicSharedMemorySize, (int)sizeof(SM3));
    cudaFuncSetAttribute(graphrec_kernel, cudaFuncAttributeMaxDynamicSharedMemorySize, (int)sizeof(SK4));

    const int SMS = 152;   // GB300: 152 SMs, one resident block each (smem-bound)
    int tasksT   = (VOCAB + 63) / 64;          // 1563
    int tasksC   = (NN + 63) / 64;             // 313
    int tasksAll = tasksT + tasksC;            // 1876
    int tasksG   = NN;                         // 20000 (1 node per task)

    int gM = (tasksAll + 1) / 2; if (gM > SMS) gM = SMS;
    int gG = (tasksG + 3) / 4;   if (gG > SMS) gG = SMS;

    prep_kernel<<<(DD * DD + 255) / 256, 256>>>(W1, W2);
    mlp_tc2_kernel<<<gM, 512, sizeof(SM3)>>>(u2e, nodes, b1, tasksT, tasksAll);
    graphrec_kernel<<<gG, 512, sizeof(SK4)>>>(u2e, nodes, nidx, nlen, b2, W3, b3, out, tasksG);
}